// round 13
// baseline (speedup 1.0000x reference)
#include <cuda_runtime.h>
#include <cuda_fp16.h>
#include <cstdint>

#define NB 8
#define LP 4096

// ======================= PTX helpers (baseline ISA only) =======================
__device__ __forceinline__ uint32_t smem_u32(const void* p){
    uint32_t a;
    asm("{ .reg .u64 t; cvta.to.shared.u64 t, %1; cvt.u32.u64 %0, t; }" : "=r"(a) : "l"(p));
    return a;
}
__device__ __forceinline__ void cpa16(uint32_t dst, const void* src, uint32_t nbytes){
    asm volatile("cp.async.cg.shared.global [%0], [%1], 16, %2;"
        :: "r"(dst), "l"(src), "r"(nbytes) : "memory");
}
#define CP_COMMIT() asm volatile("cp.async.commit_group;" ::: "memory")
#define CP_WAIT1()  asm volatile("cp.async.wait_group 1;" ::: "memory")

__device__ __forceinline__ void ldsm4(uint32_t* r, uint32_t a){
    asm volatile("ldmatrix.sync.aligned.m8n8.x4.shared.b16 {%0,%1,%2,%3}, [%4];"
        : "=r"(r[0]), "=r"(r[1]), "=r"(r[2]), "=r"(r[3]) : "r"(a));
}
__device__ __forceinline__ void mma16816(float* c, const uint32_t* a, uint32_t b0, uint32_t b1){
    asm volatile("mma.sync.aligned.m16n8k16.row.col.f32.f16.f16.f32 "
        "{%0,%1,%2,%3}, {%4,%5,%6,%7}, {%8,%9}, {%0,%1,%2,%3};"
        : "+f"(c[0]), "+f"(c[1]), "+f"(c[2]), "+f"(c[3])
        : "r"(a[0]), "r"(a[1]), "r"(a[2]), "r"(a[3]), "r"(b0), "r"(b1));
}
#define SW128(o) ((o) ^ (((o) >> 3) & 0x70))

// ======================= device scratch =======================
__device__ __half g_xa[(size_t)NB*LP*512];
__device__ __half g_y0[(size_t)NB*LP*512];
__device__ __half g_t0[(size_t)NB*LP*256];
__device__ __half g_b1[(size_t)NB*LP*256];
__device__ __half g_t1[(size_t)NB*LP*256];
__device__ __half g_b2[(size_t)NB*LP*256];
__device__ float g_value[(size_t)NB*LP*256];
__device__ float g_off [(size_t)NB*LP*64];
__device__ float g_awL [(size_t)NB*LP*32];
__device__ __half g_sm[(size_t)NB*LP*256];
__device__ __half g_at[(size_t)NB*LP*256];

__device__ __half g_wcv1[512*512];
__device__ __half g_wc0[256*2304];
__device__ __half g_wc1[256*2304];
__device__ __half g_wc2[256*2304];
__device__ __half g_wc3[256*2304];
__device__ __half g_wct[384*256];
__device__ float  g_bct[384];
__device__ __half g_wo[256*256];
__device__ __half g_wv2[512*1280];

__device__ __forceinline__ float silu_f(float v){ return v / (1.f + __expf(-v)); }
__device__ __forceinline__ uint32_t packh2(float a, float b){
    __half2 hh = __floats2half2_rn(a, b);
    return *(uint32_t*)&hh;
}

// ======================= conversion kernels =======================
__global__ void k_cvt_x(const float* __restrict__ x){
    __shared__ float t[32][33];
    int b = blockIdx.z, l0 = blockIdx.x<<5, c0 = blockIdx.y<<5;
    int tx = threadIdx.x, ty = threadIdx.y;
#pragma unroll
    for (int i=0;i<32;i+=8)
        t[ty+i][tx] = x[((size_t)((b<<9)+(c0+ty+i))<<12) + l0 + tx];
    __syncthreads();
#pragma unroll
    for (int i=0;i<32;i+=8){
        size_t o = ((size_t)((b<<12)+(l0+ty+i))<<9) + c0 + tx;
        g_xa[o] = __float2half(t[tx][ty+i]);
    }
}

__global__ void k_cvt_w(const float* __restrict__ cv1w, const float* __restrict__ cv2w,
                        const float* __restrict__ c0, const float* __restrict__ c1,
                        const float* __restrict__ c2, const float* __restrict__ c3,
                        const float* __restrict__ vw, const float* __restrict__ vb2,
                        const float* __restrict__ ow2, const float* __restrict__ ob2,
                        const float* __restrict__ aw2, const float* __restrict__ ab2,
                        const float* __restrict__ outw){
    int which = blockIdx.y;
    size_t i = (size_t)blockIdx.x*256 + threadIdx.x;
    if (which == 0){
        if (i >= (size_t)512*512) return;
        g_wcv1[i] = __float2half(cv1w[i]);
    } else if (which == 1){
        if (i >= (size_t)512*1280) return;
        g_wv2[i] = __float2half(cv2w[i]);
    } else if (which <= 5){
        if (i >= (size_t)256*2304) return;
        const float* src = (which==2)?c0:(which==3)?c1:(which==4)?c2:c3;
        __half *dh = (which==2)?g_wc0:(which==3)?g_wc1:(which==4)?g_wc2:g_wc3;
        int o = (int)(i / 2304);
        int k = (int)(i - (size_t)o*2304);
        int j = k >> 8, ic = k & 255;
        dh[i] = __float2half(src[((size_t)o*256 + ic)*9 + j]);
    } else if (which == 6){
        if (i >= (size_t)384*256) return;
        int n = (int)(i >> 8), c = (int)(i & 255);
        float v = 0.f;
        if (n < 256)       v = vw[(size_t)c*256 + n];
        else if (n < 320)  v = ow2[(size_t)c*64 + (n-256)];
        else if (n < 352)  v = aw2[(size_t)c*32 + (n-320)];
        g_wct[i] = __float2half(v);
        if (c == 0){
            float bv = 0.f;
            if (n < 256) bv = vb2[n];
            else if (n < 320) bv = ob2[n-256];
            else if (n < 352) bv = ab2[n-320];
            g_bct[n] = bv;
        }
    } else {
        if (i >= (size_t)256*256) return;
        int n = (int)(i >> 8), c = (int)(i & 255);
        g_wo[i] = __float2half(outw[(size_t)c*256 + n]);
    }
}

// ======================= main GEMM (pure fp16 mma.sync, fp32 accum) =======================
// CTA tile 64(m) x 128(n) x 64(k). 8 warps (2x4), warp tile 32x32.
// SMEM buffer (24KB): A 8KB (64 rows x 128B SW128); B 16KB (128 rows x 128B SW128).
// 3-deep ring = 72KB; 3 CTAs/SM.
#define BUFB 24576
#define SMEM_BYTES (3*BUFB)

__global__ __launch_bounds__(256, 3) void k_gemm(int stage, const float* __restrict__ ebias,
                                                 float* __restrict__ dout)
{
    extern __shared__ char smc[];
    const uint32_t sb = smem_u32(smc);
    const int tid = threadIdx.x;
    const int wid = tid >> 5, lid = tid & 31;
    const int b  = blockIdx.z;
    const int l0 = blockIdx.y << 6;          // 64-row M tile
    const int n0 = blockIdx.x << 7;

    int K;
    const __half* wgt;
    switch (stage){
        case 0: K = 512;  wgt = g_wcv1; break;
        case 1: K = 2304; wgt = g_wc0;  break;
        case 2: K = 2304; wgt = g_wc1;  break;
        case 3: K = 2304; wgt = g_wc2;  break;
        case 4: K = 2304; wgt = g_wc3;  break;
        case 5: K = 256;  wgt = g_wct;  break;
        case 6: K = 256;  wgt = g_wo;   break;
        default:K = 1280; wgt = g_wv2;  break;
    }
    const int NC = K >> 6;

    float acc[2][4][4];
#pragma unroll
    for (int i=0;i<2;i++)
#pragma unroll
    for (int j=0;j<4;j++)
#pragma unroll
    for (int e=0;e<4;e++) acc[i][j][e] = 0.f;

    const int wm = wid >> 2, wn = wid & 3;   // warp 32(m) x 32(n)

    auto issue = [&](int cc){
        const __half *aa; int ach, acb, ady = 0, adx = 0; bool acv = false;
        const int k0c = cc << 6;
        if (stage == 0){ aa = g_xa; ach = 512; acb = k0c; }
        else if (stage <= 4){
            int j = cc >> 2; int jd = j / 3;
            ady = jd - 1; adx = j - jd*3 - 1; acv = true;
            int ic0 = (cc & 3) << 6;
            if (stage == 1){ aa = g_y0; ach = 512; acb = 256 + ic0; }
            else if (stage == 2){ aa = g_t0; ach = 256; acb = ic0; }
            else if (stage == 3){ aa = g_b1; ach = 256; acb = ic0; }
            else { aa = g_t1; ach = 256; acb = ic0; }
        }
        else if (stage == 5){ aa = g_b2; ach = 256; acb = k0c; }
        else if (stage == 6){ aa = g_sm; ach = 256; acb = k0c; }
        else {
            if (k0c < 512)      { aa = g_y0; ach = 512; acb = k0c; }
            else if (k0c < 768) { aa = g_b1; ach = 256; acb = k0c - 512; }
            else if (k0c < 1024){ aa = g_b2; ach = 256; acb = k0c - 768; }
            else                { aa = g_at; ach = 256; acb = k0c - 1024; }
        }
        uint32_t base = sb + (uint32_t)(cc % 3) * BUFB;
        // ---- A: 64 rows x 128B SW128, 512 units, 2 per thread ----
#pragma unroll
        for (int it2 = 0; it2 < 2; it2++){
            int it = tid + (it2 << 8);        // 0..511
            int m = it >> 3, u = it & 7;
            uint32_t o = ((uint32_t)m << 7) + ((uint32_t)u << 4);
            size_t off = 0; uint32_t nb = 16;
            if (acv){
                int p = l0 + m;
                int sy = (p >> 6) + ady, sx = (p & 63) + adx;
                if ((unsigned)sy < 64u && (unsigned)sx < 64u)
                    off = (size_t)((b<<12) + (sy<<6) + sx) * ach + acb + (u<<3);
                else nb = 0;
            } else {
                off = (size_t)((b<<12) + l0 + m) * ach + acb + (u<<3);
            }
            cpa16(base + SW128(o), aa + off, nb);
        }
        // ---- B: 128 rows x 128B SW128 ----
#pragma unroll
        for (int it2 = 0; it2 < 4; it2++){
            int it = tid + (it2 << 8);
            int n = it >> 3, u = it & 7;
            uint32_t o = ((uint32_t)n << 7) + ((uint32_t)u << 4);
            size_t woff = (size_t)(n0 + n) * K + k0c + (u << 3);
            cpa16(base + 8192 + SW128(o), wgt + woff, 16);
        }
        CP_COMMIT();
    };

    issue(0);
    issue(1);
    for (int cc = 0; cc < NC; cc++){
        CP_WAIT1();
        __syncthreads();
        if (cc + 2 < NC) issue(cc + 2);
        uint32_t ua = sb + (uint32_t)(cc % 3) * BUFB;
        uint32_t ub = ua + 8192u;
        const int mat = lid >> 3, r8 = lid & 7;
#pragma unroll
        for (int ks = 0; ks < 4; ks++){
            uint32_t af[2][4], bf[2][4];
#pragma unroll
            for (int mi = 0; mi < 2; mi++){
                int row = (wm << 5) + (mi << 4) + ((mat & 1) << 3) + r8;
                uint32_t o = ((uint32_t)row << 7) + (ks << 5) + ((mat >> 1) << 4);
                ldsm4(af[mi], ua + SW128(o));
            }
#pragma unroll
            for (int bi = 0; bi < 2; bi++){
                int row = (wn << 5) + (bi << 4) + ((mat >> 1) << 3) + r8;
                uint32_t o = ((uint32_t)row << 7) + (ks << 5) + ((mat & 1) << 4);
                ldsm4(bf[bi], ub + SW128(o));
            }
#pragma unroll
            for (int mi = 0; mi < 2; mi++)
#pragma unroll
            for (int ni = 0; ni < 4; ni++)
                mma16816(acc[mi][ni], af[mi],
                         bf[ni >> 1][(ni & 1) << 1], bf[ni >> 1][((ni & 1) << 1) + 1]);
        }
    }

    // ---------------- epilogue ----------------
    const int qr = lid >> 2;
    const int qc = (lid & 3) << 1;
#pragma unroll
    for (int mi = 0; mi < 2; mi++){
#pragma unroll
        for (int ni = 0; ni < 4; ni++){
            float* c = acc[mi][ni];
            int ch = (wn << 5) + (ni << 3) + qc;
            int r0 = (wm << 5) + (mi << 4) + qr;
            int r1 = r0 + 8;

            if (stage <= 4){
                __half* dd; int OC;
                if (stage == 0){ dd = g_y0; OC = 512; }
                else if (stage == 1){ dd = g_t0; OC = 256; }
                else if (stage == 2){ dd = g_b1; OC = 256; }
                else if (stage == 3){ dd = g_t1; OC = 256; }
                else { dd = g_b2; OC = 256; }
#pragma unroll
                for (int h2 = 0; h2 < 2; h2++){
                    int r = h2 ? r1 : r0;
                    size_t o = ((size_t)((b<<12) + l0 + r)) * OC + n0 + ch;
                    *(uint32_t*)&dd[o] = packh2(silu_f(c[2*h2]), silu_f(c[2*h2+1]));
                }
            } else if (stage == 5){
#pragma unroll
                for (int h2 = 0; h2 < 2; h2++){
                    int r = h2 ? r1 : r0;
                    size_t bl2 = (size_t)(b<<12) + l0 + r;
#pragma unroll
                    for (int e = 0; e < 2; e++){
                        int ng = n0 + ch + e;
                        float v = c[2*h2 + e] + g_bct[ng];
                        if (ng < 256)      g_value[bl2*256 + ng] = v;
                        else if (ng < 320) g_off [bl2*64 + (ng - 256)] = v;
                        else if (ng < 352) g_awL [bl2*32 + (ng - 320)] = v;
                    }
                }
            } else if (stage == 6){
#pragma unroll
                for (int h2 = 0; h2 < 2; h2++){
                    int r = h2 ? r1 : r0;
                    float v0 = c[2*h2]     + ebias[n0 + ch];
                    float v1 = c[2*h2 + 1] + ebias[n0 + ch + 1];
                    size_t o = ((size_t)((b<<12) + l0 + r)) * 256 + n0 + ch;
                    *(uint32_t*)&g_at[o] = packh2(v0, v1);
                }
            } else {
#pragma unroll
                for (int h2 = 0; h2 < 2; h2++){
                    int r = h2 ? r1 : r0;
#pragma unroll
                    for (int e = 0; e < 2; e++){
                        float v = silu_f(c[2*h2 + e]);
                        dout[((size_t)((b << 9) + n0 + ch + e) << 12) + l0 + r] = v;
                    }
                }
            }
        }
    }
}

// ======================= deformable sampling =======================
__global__ void k_sample(const float* __restrict__ bbox){
    int g = blockIdx.x * blockDim.x + threadIdx.x;
    if (g >= NB * LP * 64) return;
    int d4 = g & 7;
    int hd = (g >> 3) & 7;
    int l  = (g >> 6) & 4095;
    int b  = g >> 18;
    size_t bl = (size_t)b * LP + l;
    float bx = bbox[bl*2 + 0];
    float by = bbox[bl*2 + 1];
    const float* op = g_off + bl*64 + hd*8;
    const float* ap = g_awL + bl*32 + hd*4;

    float a0 = ap[0], a1 = ap[1], a2 = ap[2], a3 = ap[3];
    float mx = fmaxf(fmaxf(a0, a1), fmaxf(a2, a3));
    float e0 = __expf(a0 - mx), e1 = __expf(a1 - mx), e2 = __expf(a2 - mx), e3 = __expf(a3 - mx);
    float inv = 1.f / (e0 + e1 + e2 + e3);
    float wp[4] = {e0*inv, e1*inv, e2*inv, e3*inv};

    const float* vb = g_value + ((size_t)b * LP) * 256 + hd*32 + (d4 << 2);
    float4 acc = make_float4(0.f, 0.f, 0.f, 0.f);
#pragma unroll
    for (int p = 0; p < 4; p++){
        float lx = bx + op[p*2 + 0] * 0.015625f;
        float ly = by + op[p*2 + 1] * 0.015625f;
        float gx = lx * 64.f - 0.5f;
        float gy = ly * 64.f - 0.5f;
        float fx = floorf(gx), fy = floorf(gy);
        float wx1 = gx - fx, wy1 = gy - fy;
        float wx0 = 1.f - wx1, wy0 = 1.f - wy1;
        int ix = (int)fx, iy = (int)fy;
        float awp = wp[p];
#pragma unroll
        for (int c2 = 0; c2 < 4; c2++){
            int cx = ix + (c2 & 1);
            int cy = iy + (c2 >> 1);
            if ((unsigned)cx < 64u && (unsigned)cy < 64u){
                float wgt = awp * ((c2 & 1) ? wx1 : wx0) * ((c2 >> 1) ? wy1 : wy0);
                float4 v = *(const float4*)&vb[(size_t)((cy << 6) + cx) * 256];
                acc.x += wgt * v.x; acc.y += wgt * v.y;
                acc.z += wgt * v.z; acc.w += wgt * v.w;
            }
        }
    }
    size_t o = bl*256 + hd*32 + (d4 << 2);
    *(uint32_t*)&g_sm[o]     = packh2(acc.x, acc.y);
    *(uint32_t*)&g_sm[o + 2] = packh2(acc.z, acc.w);
}

// ======================= launch =======================
extern "C" void kernel_launch(void* const* d_in, const int* in_sizes, int n_in,
                              void* d_out, int out_size) {
    const float* x    = (const float*)d_in[0];
    const float* bbox = (const float*)d_in[1];
    const float* cv1w = (const float*)d_in[3];
    const float* m0c1 = (const float*)d_in[4];
    const float* m0c2 = (const float*)d_in[5];
    const float* m1c1 = (const float*)d_in[6];
    const float* m1c2 = (const float*)d_in[7];
    const float* vw   = (const float*)d_in[8];
    const float* vb   = (const float*)d_in[9];
    const float* ow   = (const float*)d_in[10];
    const float* ob   = (const float*)d_in[11];
    const float* aww  = (const float*)d_in[12];
    const float* awb  = (const float*)d_in[13];
    const float* outw = (const float*)d_in[14];
    const float* outb = (const float*)d_in[15];
    const float* cv2w = (const float*)d_in[16];

    cudaFuncSetAttribute(k_gemm, cudaFuncAttributeMaxDynamicSharedMemorySize, SMEM_BYTES);

    k_cvt_x<<<dim3(128, 16, NB), dim3(32, 8)>>>(x);
    k_cvt_w<<<dim3(2560, 8), 256>>>(cv1w, cv2w, m0c1, m0c2, m1c1, m1c2,
                                    vw, vb, ow, ob, aww, awb, outw);

    k_gemm<<<dim3(4, 64, NB), 256, SMEM_BYTES>>>(0, nullptr, nullptr);   // cv1
    k_gemm<<<dim3(2, 64, NB), 256, SMEM_BYTES>>>(1, nullptr, nullptr);   // m0_cv1
    k_gemm<<<dim3(2, 64, NB), 256, SMEM_BYTES>>>(2, nullptr, nullptr);   // m0_cv2
    k_gemm<<<dim3(2, 64, NB), 256, SMEM_BYTES>>>(3, nullptr, nullptr);   // m1_cv1
    k_gemm<<<dim3(2, 64, NB), 256, SMEM_BYTES>>>(4, nullptr, nullptr);   // m1_cv2
    k_gemm<<<dim3(3, 64, NB), 256, SMEM_BYTES>>>(5, nullptr, nullptr);   // fused projections
    k_sample<<<(NB * LP * 64 + 255) / 256, 256>>>(bbox);
    k_gemm<<<dim3(2, 64, NB), 256, SMEM_BYTES>>>(6, outb, nullptr);      // out projection
    k_gemm<<<dim3(4, 64, NB), 256, SMEM_BYTES>>>(7, nullptr, (float*)d_out); // cv2
}

// round 15
// speedup vs baseline: 1.3162x; 1.3162x over previous
#include <cuda_runtime.h>
#include <cuda_fp16.h>
#include <cstdint>

#define NB 8
#define LP 4096

// ======================= PTX helpers (baseline ISA only) =======================
__device__ __forceinline__ uint32_t smem_u32(const void* p){
    uint32_t a;
    asm("{ .reg .u64 t; cvta.to.shared.u64 t, %1; cvt.u32.u64 %0, t; }" : "=r"(a) : "l"(p));
    return a;
}
__device__ __forceinline__ void cpa16(uint32_t dst, const void* src, uint32_t nbytes){
    asm volatile("cp.async.cg.shared.global [%0], [%1], 16, %2;"
        :: "r"(dst), "l"(src), "r"(nbytes) : "memory");
}
#define CP_COMMIT() asm volatile("cp.async.commit_group;" ::: "memory")
#define CP_WAIT1()  asm volatile("cp.async.wait_group 1;" ::: "memory")

__device__ __forceinline__ void ldsm4(uint32_t* r, uint32_t a){
    asm volatile("ldmatrix.sync.aligned.m8n8.x4.shared.b16 {%0,%1,%2,%3}, [%4];"
        : "=r"(r[0]), "=r"(r[1]), "=r"(r[2]), "=r"(r[3]) : "r"(a));
}
__device__ __forceinline__ void ldgv4(uint32_t* r, const void* p){
    asm volatile("ld.global.nc.v4.u32 {%0,%1,%2,%3}, [%4];"
        : "=r"(r[0]), "=r"(r[1]), "=r"(r[2]), "=r"(r[3]) : "l"(p));
}
__device__ __forceinline__ void mma16816(float* c, const uint32_t* a, uint32_t b0, uint32_t b1){
    asm volatile("mma.sync.aligned.m16n8k16.row.col.f32.f16.f16.f32 "
        "{%0,%1,%2,%3}, {%4,%5,%6,%7}, {%8,%9}, {%0,%1,%2,%3};"
        : "+f"(c[0]), "+f"(c[1]), "+f"(c[2]), "+f"(c[3])
        : "r"(a[0]), "r"(a[1]), "r"(a[2]), "r"(a[3]), "r"(b0), "r"(b1));
}
#define SW128(o) ((o) ^ (((o) >> 3) & 0x70))

// ======================= device scratch =======================
__device__ __half g_xa[(size_t)NB*LP*512];
__device__ __half g_y0[(size_t)NB*LP*512];
__device__ __half g_t0[(size_t)NB*LP*256];
__device__ __half g_b1[(size_t)NB*LP*256];
__device__ __half g_t1[(size_t)NB*LP*256];
__device__ __half g_b2[(size_t)NB*LP*256];
__device__ float g_value[(size_t)NB*LP*256];
__device__ float g_off [(size_t)NB*LP*64];
__device__ float g_awL [(size_t)NB*LP*32];
__device__ __half g_sm[(size_t)NB*LP*256];
__device__ __half g_at[(size_t)NB*LP*256];

// weights, stored PERMUTED into mma B-fragment order:
// tile (nt,kt) of 16x16 -> 512B block at ((nt*(K/16)+kt)*256 halves);
// within tile: thread t (0..31) holds 8 halves (4 b32 = frags j0..j3) at t*8 + j*2 + (k&1)
__device__ __half g_wcv1[512*512];
__device__ __half g_wc0[256*2304];
__device__ __half g_wc1[256*2304];
__device__ __half g_wc2[256*2304];
__device__ __half g_wc3[256*2304];
__device__ __half g_wct[384*256];
__device__ float  g_bct[384];
__device__ __half g_wo[256*256];
__device__ __half g_wv2[512*1280];

__device__ __forceinline__ size_t permpos(int n, int k, int K){
    size_t nt = (size_t)(n >> 4), kt = (size_t)(k >> 4);
    int nr = n & 15, kr = k & 15;
    int j = ((nr >> 3) << 1) | (kr >> 3);
    int t = ((nr & 7) << 2) | ((kr & 7) >> 1);
    return ((nt * (size_t)(K >> 4) + kt) << 8) + (size_t)((t << 3) + (j << 1) + (kr & 1));
}

__device__ __forceinline__ float silu_f(float v){ return v / (1.f + __expf(-v)); }
__device__ __forceinline__ uint32_t packh2(float a, float b){
    __half2 hh = __floats2half2_rn(a, b);
    return *(uint32_t*)&hh;
}

// ======================= conversion kernels =======================
__global__ void k_cvt_x(const float* __restrict__ x){
    __shared__ float t[32][33];
    int b = blockIdx.z, l0 = blockIdx.x<<5, c0 = blockIdx.y<<5;
    int tx = threadIdx.x, ty = threadIdx.y;
#pragma unroll
    for (int i=0;i<32;i+=8)
        t[ty+i][tx] = x[((size_t)((b<<9)+(c0+ty+i))<<12) + l0 + tx];
    __syncthreads();
#pragma unroll
    for (int i=0;i<32;i+=8){
        size_t o = ((size_t)((b<<12)+(l0+ty+i))<<9) + c0 + tx;
        g_xa[o] = __float2half(t[tx][ty+i]);
    }
}

__global__ void k_cvt_w(const float* __restrict__ cv1w, const float* __restrict__ cv2w,
                        const float* __restrict__ c0, const float* __restrict__ c1,
                        const float* __restrict__ c2, const float* __restrict__ c3,
                        const float* __restrict__ vw, const float* __restrict__ vb2,
                        const float* __restrict__ ow2, const float* __restrict__ ob2,
                        const float* __restrict__ aw2, const float* __restrict__ ab2,
                        const float* __restrict__ outw){
    int which = blockIdx.y;
    size_t i = (size_t)blockIdx.x*256 + threadIdx.x;
    if (which == 0){
        if (i >= (size_t)512*512) return;
        int n = (int)(i >> 9), k = (int)(i & 511);
        g_wcv1[permpos(n, k, 512)] = __float2half(cv1w[i]);
    } else if (which == 1){
        if (i >= (size_t)512*1280) return;
        int n = (int)(i / 1280), k = (int)(i - (size_t)n*1280);
        g_wv2[permpos(n, k, 1280)] = __float2half(cv2w[i]);
    } else if (which <= 5){
        if (i >= (size_t)256*2304) return;
        const float* src = (which==2)?c0:(which==3)?c1:(which==4)?c2:c3;
        __half *dh = (which==2)?g_wc0:(which==3)?g_wc1:(which==4)?g_wc2:g_wc3;
        int n = (int)(i / 2304);
        int k = (int)(i - (size_t)n*2304);
        int j = k >> 8, ic = k & 255;
        dh[permpos(n, k, 2304)] = __float2half(src[((size_t)n*256 + ic)*9 + j]);
    } else if (which == 6){
        if (i >= (size_t)384*256) return;
        int n = (int)(i >> 8), c = (int)(i & 255);
        float v = 0.f;
        if (n < 256)       v = vw[(size_t)c*256 + n];
        else if (n < 320)  v = ow2[(size_t)c*64 + (n-256)];
        else if (n < 352)  v = aw2[(size_t)c*32 + (n-320)];
        g_wct[permpos(n, c, 256)] = __float2half(v);
        if (c == 0){
            float bv = 0.f;
            if (n < 256) bv = vb2[n];
            else if (n < 320) bv = ob2[n-256];
            else if (n < 352) bv = ab2[n-320];
            g_bct[n] = bv;
        }
    } else {
        if (i >= (size_t)256*256) return;
        int n = (int)(i >> 8), c = (int)(i & 255);
        g_wo[permpos(n, c, 256)] = __float2half(outw[(size_t)c*256 + n]);
    }
}

// ======================= main GEMM (pure fp16 mma.sync, fp32 accum) =======================
// CTA tile 128x128x64. 8 warps (2x4), warp tile 64x32.
// A: smem (16KB buffer: 128 rows x 128B SW128), 3-deep ring = 48KB, 2 CTAs/SM.
// B: direct global->register loads from fragment-permuted weights (L2-resident).
#define BUFB 16384
#define SMEM_BYTES (3*BUFB)

__global__ __launch_bounds__(256, 2) void k_gemm(int stage, const float* __restrict__ ebias,
                                                 float* __restrict__ dout)
{
    extern __shared__ char smc[];
    const uint32_t sb = smem_u32(smc);
    const int tid = threadIdx.x;
    const int wid = tid >> 5, lid = tid & 31;
    const int b  = blockIdx.z;
    const int l0 = blockIdx.y << 7;
    const int n0 = blockIdx.x << 7;

    int K;
    const __half* wgt;
    switch (stage){
        case 0: K = 512;  wgt = g_wcv1; break;
        case 1: K = 2304; wgt = g_wc0;  break;
        case 2: K = 2304; wgt = g_wc1;  break;
        case 3: K = 2304; wgt = g_wc2;  break;
        case 4: K = 2304; wgt = g_wc3;  break;
        case 5: K = 256;  wgt = g_wct;  break;
        case 6: K = 256;  wgt = g_wo;   break;
        default:K = 1280; wgt = g_wv2;  break;
    }
    const int NC = K >> 6;

    float acc[4][4][4];
#pragma unroll
    for (int i=0;i<4;i++)
#pragma unroll
    for (int j=0;j<4;j++)
#pragma unroll
    for (int e=0;e<4;e++) acc[i][j][e] = 0.f;

    const int wm = wid >> 2, wn = wid & 3;
    const int mat = lid >> 3, r8 = lid & 7;

    // permuted-weight base pointers for this warp's two n-tiles
    const size_t ktiles = (size_t)(K >> 4);
    const __half* wb0 = wgt + ((((size_t)(n0 >> 4) + (wn << 1) + 0) * ktiles) << 8) + (lid << 3);
    const __half* wb1 = wgt + ((((size_t)(n0 >> 4) + (wn << 1) + 1) * ktiles) << 8) + (lid << 3);

    auto issue = [&](int cc){
        const __half *aa; int ach, acb, ady = 0, adx = 0; bool acv = false;
        const int k0c = cc << 6;
        if (stage == 0){ aa = g_xa; ach = 512; acb = k0c; }
        else if (stage <= 4){
            int j = cc >> 2; int jd = j / 3;
            ady = jd - 1; adx = j - jd*3 - 1; acv = true;
            int ic0 = (cc & 3) << 6;
            if (stage == 1){ aa = g_y0; ach = 512; acb = 256 + ic0; }
            else if (stage == 2){ aa = g_t0; ach = 256; acb = ic0; }
            else if (stage == 3){ aa = g_b1; ach = 256; acb = ic0; }
            else { aa = g_t1; ach = 256; acb = ic0; }
        }
        else if (stage == 5){ aa = g_b2; ach = 256; acb = k0c; }
        else if (stage == 6){ aa = g_sm; ach = 256; acb = k0c; }
        else {
            if (k0c < 512)      { aa = g_y0; ach = 512; acb = k0c; }
            else if (k0c < 768) { aa = g_b1; ach = 256; acb = k0c - 512; }
            else if (k0c < 1024){ aa = g_b2; ach = 256; acb = k0c - 768; }
            else                { aa = g_at; ach = 256; acb = k0c - 1024; }
        }
        uint32_t base = sb + (uint32_t)(cc % 3) * BUFB;
        // A: 128 rows x 128B SW128, 1024 units, 4 per thread
#pragma unroll
        for (int it2 = 0; it2 < 4; it2++){
            int it = tid + (it2 << 8);
            int m = it >> 3, u = it & 7;
            uint32_t o = ((uint32_t)m << 7) + ((uint32_t)u << 4);
            size_t off = 0; uint32_t nb = 16;
            if (acv){
                int p = l0 + m;
                int sy = (p >> 6) + ady, sx = (p & 63) + adx;
                if ((unsigned)sy < 64u && (unsigned)sx < 64u)
                    off = (size_t)((b<<12) + (sy<<6) + sx) * ach + acb + (u<<3);
                else nb = 0;
            } else {
                off = (size_t)((b<<12) + l0 + m) * ach + acb + (u<<3);
            }
            cpa16(base + SW128(o), aa + off, nb);
        }
        CP_COMMIT();
    };

    issue(0);
    issue(1);
    for (int cc = 0; cc < NC; cc++){
        CP_WAIT1();
        __syncthreads();
        if (cc + 2 < NC) issue(cc + 2);
        uint32_t ua = sb + (uint32_t)(cc % 3) * BUFB;
        const __half* wc0 = wb0 + ((size_t)(cc << 2) << 8);
        const __half* wc1 = wb1 + ((size_t)(cc << 2) << 8);

        uint32_t bfr[2][2][4];
        // B fragments for ks=0
        ldgv4(bfr[0][0], wc0);
        ldgv4(bfr[0][1], wc1);

#pragma unroll
        for (int ks = 0; ks < 4; ks++){
            const int cur = ks & 1, nxt = cur ^ 1;
            if (ks < 3){
                ldgv4(bfr[nxt][0], wc0 + ((ks + 1) << 8));
                ldgv4(bfr[nxt][1], wc1 + ((ks + 1) << 8));
            }
            uint32_t af[4][4];
#pragma unroll
            for (int mi = 0; mi < 4; mi++){
                int row = (wm << 6) + (mi << 4) + ((mat & 1) << 3) + r8;
                uint32_t o = ((uint32_t)row << 7) + (ks << 5) + ((mat >> 1) << 4);
                ldsm4(af[mi], ua + SW128(o));
            }
#pragma unroll
            for (int mi = 0; mi < 4; mi++)
#pragma unroll
            for (int ni = 0; ni < 4; ni++)
                mma16816(acc[mi][ni], af[mi],
                         bfr[cur][ni >> 1][(ni & 1) << 1], bfr[cur][ni >> 1][((ni & 1) << 1) + 1]);
        }
    }

    // ---------------- epilogue ----------------
    const int qr = lid >> 2;
    const int qc = (lid & 3) << 1;
#pragma unroll
    for (int mi = 0; mi < 4; mi++){
#pragma unroll
        for (int ni = 0; ni < 4; ni++){
            float* c = acc[mi][ni];
            int ch = (wn << 5) + (ni << 3) + qc;
            int r0 = (wm << 6) + (mi << 4) + qr;
            int r1 = r0 + 8;

            if (stage <= 4){
                __half* dd; int OC;
                if (stage == 0){ dd = g_y0; OC = 512; }
                else if (stage == 1){ dd = g_t0; OC = 256; }
                else if (stage == 2){ dd = g_b1; OC = 256; }
                else if (stage == 3){ dd = g_t1; OC = 256; }
                else { dd = g_b2; OC = 256; }
#pragma unroll
                for (int h2 = 0; h2 < 2; h2++){
                    int r = h2 ? r1 : r0;
                    size_t o = ((size_t)((b<<12) + l0 + r)) * OC + n0 + ch;
                    *(uint32_t*)&dd[o] = packh2(silu_f(c[2*h2]), silu_f(c[2*h2+1]));
                }
            } else if (stage == 5){
#pragma unroll
                for (int h2 = 0; h2 < 2; h2++){
                    int r = h2 ? r1 : r0;
                    size_t bl2 = (size_t)(b<<12) + l0 + r;
#pragma unroll
                    for (int e = 0; e < 2; e++){
                        int ng = n0 + ch + e;
                        float v = c[2*h2 + e] + g_bct[ng];
                        if (ng < 256)      g_value[bl2*256 + ng] = v;
                        else if (ng < 320) g_off [bl2*64 + (ng - 256)] = v;
                        else if (ng < 352) g_awL [bl2*32 + (ng - 320)] = v;
                    }
                }
            } else if (stage == 6){
#pragma unroll
                for (int h2 = 0; h2 < 2; h2++){
                    int r = h2 ? r1 : r0;
                    float v0 = c[2*h2]     + ebias[n0 + ch];
                    float v1 = c[2*h2 + 1] + ebias[n0 + ch + 1];
                    size_t o = ((size_t)((b<<12) + l0 + r)) * 256 + n0 + ch;
                    *(uint32_t*)&g_at[o] = packh2(v0, v1);
                }
            } else {
#pragma unroll
                for (int h2 = 0; h2 < 2; h2++){
                    int r = h2 ? r1 : r0;
#pragma unroll
                    for (int e = 0; e < 2; e++){
                        float v = silu_f(c[2*h2 + e]);
                        dout[((size_t)((b << 9) + n0 + ch + e) << 12) + l0 + r] = v;
                    }
                }
            }
        }
    }
}

// ======================= deformable sampling =======================
__global__ void k_sample(const float* __restrict__ bbox){
    int g = blockIdx.x * blockDim.x + threadIdx.x;
    if (g >= NB * LP * 64) return;
    int d4 = g & 7;
    int hd = (g >> 3) & 7;
    int l  = (g >> 6) & 4095;
    int b  = g >> 18;
    size_t bl = (size_t)b * LP + l;
    float bx = bbox[bl*2 + 0];
    float by = bbox[bl*2 + 1];
    const float* op = g_off + bl*64 + hd*8;
    const float* ap = g_awL + bl*32 + hd*4;

    float a0 = ap[0], a1 = ap[1], a2 = ap[2], a3 = ap[3];
    float mx = fmaxf(fmaxf(a0, a1), fmaxf(a2, a3));
    float e0 = __expf(a0 - mx), e1 = __expf(a1 - mx), e2 = __expf(a2 - mx), e3 = __expf(a3 - mx);
    float inv = 1.f / (e0 + e1 + e2 + e3);
    float wp[4] = {e0*inv, e1*inv, e2*inv, e3*inv};

    const float* vb = g_value + ((size_t)b * LP) * 256 + hd*32 + (d4 << 2);
    float4 acc = make_float4(0.f, 0.f, 0.f, 0.f);
#pragma unroll
    for (int p = 0; p < 4; p++){
        float lx = bx + op[p*2 + 0] * 0.015625f;
        float ly = by + op[p*2 + 1] * 0.015625f;
        float gx = lx * 64.f - 0.5f;
        float gy = ly * 64.f - 0.5f;
        float fx = floorf(gx), fy = floorf(gy);
        float wx1 = gx - fx, wy1 = gy - fy;
        float wx0 = 1.f - wx1, wy0 = 1.f - wy1;
        int ix = (int)fx, iy = (int)fy;
        float awp = wp[p];
#pragma unroll
        for (int c2 = 0; c2 < 4; c2++){
            int cx = ix + (c2 & 1);
            int cy = iy + (c2 >> 1);
            if ((unsigned)cx < 64u && (unsigned)cy < 64u){
                float wgt = awp * ((c2 & 1) ? wx1 : wx0) * ((c2 >> 1) ? wy1 : wy0);
                float4 v = *(const float4*)&vb[(size_t)((cy << 6) + cx) * 256];
                acc.x += wgt * v.x; acc.y += wgt * v.y;
                acc.z += wgt * v.z; acc.w += wgt * v.w;
            }
        }
    }
    size_t o = bl*256 + hd*32 + (d4 << 2);
    *(uint32_t*)&g_sm[o]     = packh2(acc.x, acc.y);
    *(uint32_t*)&g_sm[o + 2] = packh2(acc.z, acc.w);
}

// ======================= launch =======================
extern "C" void kernel_launch(void* const* d_in, const int* in_sizes, int n_in,
                              void* d_out, int out_size) {
    const float* x    = (const float*)d_in[0];
    const float* bbox = (const float*)d_in[1];
    const float* cv1w = (const float*)d_in[3];
    const float* m0c1 = (const float*)d_in[4];
    const float* m0c2 = (const float*)d_in[5];
    const float* m1c1 = (const float*)d_in[6];
    const float* m1c2 = (const float*)d_in[7];
    const float* vw   = (const float*)d_in[8];
    const float* vb   = (const float*)d_in[9];
    const float* ow   = (const float*)d_in[10];
    const float* ob   = (const float*)d_in[11];
    const float* aww  = (const float*)d_in[12];
    const float* awb  = (const float*)d_in[13];
    const float* outw = (const float*)d_in[14];
    const float* outb = (const float*)d_in[15];
    const float* cv2w = (const float*)d_in[16];

    cudaFuncSetAttribute(k_gemm, cudaFuncAttributeMaxDynamicSharedMemorySize, SMEM_BYTES);

    k_cvt_x<<<dim3(128, 16, NB), dim3(32, 8)>>>(x);
    k_cvt_w<<<dim3(2560, 8), 256>>>(cv1w, cv2w, m0c1, m0c2, m1c1, m1c2,
                                    vw, vb, ow, ob, aww, awb, outw);

    k_gemm<<<dim3(4, 32, NB), 256, SMEM_BYTES>>>(0, nullptr, nullptr);   // cv1
    k_gemm<<<dim3(2, 32, NB), 256, SMEM_BYTES>>>(1, nullptr, nullptr);   // m0_cv1
    k_gemm<<<dim3(2, 32, NB), 256, SMEM_BYTES>>>(2, nullptr, nullptr);   // m0_cv2
    k_gemm<<<dim3(2, 32, NB), 256, SMEM_BYTES>>>(3, nullptr, nullptr);   // m1_cv1
    k_gemm<<<dim3(2, 32, NB), 256, SMEM_BYTES>>>(4, nullptr, nullptr);   // m1_cv2
    k_gemm<<<dim3(3, 32, NB), 256, SMEM_BYTES>>>(5, nullptr, nullptr);   // fused projections
    k_sample<<<(NB * LP * 64 + 255) / 256, 256>>>(bbox);
    k_gemm<<<dim3(2, 32, NB), 256, SMEM_BYTES>>>(6, outb, nullptr);      // out projection
    k_gemm<<<dim3(4, 32, NB), 256, SMEM_BYTES>>>(7, nullptr, (float*)d_out); // cv2
}

// round 16
// speedup vs baseline: 1.4767x; 1.1220x over previous
#include <cuda_runtime.h>
#include <cuda_fp16.h>
#include <cstdint>

#define NB 8
#define LP 4096

// ======================= PTX helpers (baseline ISA only) =======================
__device__ __forceinline__ uint32_t smem_u32(const void* p){
    uint32_t a;
    asm("{ .reg .u64 t; cvta.to.shared.u64 t, %1; cvt.u32.u64 %0, t; }" : "=r"(a) : "l"(p));
    return a;
}
__device__ __forceinline__ void cpa16(uint32_t dst, const void* src, uint32_t nbytes){
    asm volatile("cp.async.cg.shared.global [%0], [%1], 16, %2;"
        :: "r"(dst), "l"(src), "r"(nbytes) : "memory");
}
#define CP_COMMIT() asm volatile("cp.async.commit_group;" ::: "memory")
#define CP_WAIT1()  asm volatile("cp.async.wait_group 1;" ::: "memory")

__device__ __forceinline__ void ldsm4(uint32_t* r, uint32_t a){
    asm volatile("ldmatrix.sync.aligned.m8n8.x4.shared.b16 {%0,%1,%2,%3}, [%4];"
        : "=r"(r[0]), "=r"(r[1]), "=r"(r[2]), "=r"(r[3]) : "r"(a));
}
__device__ __forceinline__ void mma16816(float* c, const uint32_t* a, uint32_t b0, uint32_t b1){
    asm volatile("mma.sync.aligned.m16n8k16.row.col.f32.f16.f16.f32 "
        "{%0,%1,%2,%3}, {%4,%5,%6,%7}, {%8,%9}, {%0,%1,%2,%3};"
        : "+f"(c[0]), "+f"(c[1]), "+f"(c[2]), "+f"(c[3])
        : "r"(a[0]), "r"(a[1]), "r"(a[2]), "r"(a[3]), "r"(b0), "r"(b1));
}
#define SW128(o) ((o) ^ (((o) >> 3) & 0x70))

// ======================= device scratch =======================
__device__ __half g_xa[(size_t)NB*LP*512];
__device__ __half g_y0[(size_t)NB*LP*512];
__device__ __half g_t0[(size_t)NB*LP*256];
__device__ __half g_b1[(size_t)NB*LP*256];
__device__ __half g_t1[(size_t)NB*LP*256];
__device__ __half g_b2[(size_t)NB*LP*256];
__device__ __half g_value[(size_t)NB*LP*256];   // fp16 now (was fp32)
__device__ float g_off [(size_t)NB*LP*64];
__device__ float g_awL [(size_t)NB*LP*32];
__device__ __half g_sm[(size_t)NB*LP*256];
__device__ __half g_at[(size_t)NB*LP*256];

__device__ __half g_wcv1[512*512];
__device__ __half g_wc0[256*2304];
__device__ __half g_wc1[256*2304];
__device__ __half g_wc2[256*2304];
__device__ __half g_wc3[256*2304];
__device__ __half g_wct[384*256];
__device__ float  g_bct[384];
__device__ __half g_wo[256*256];
__device__ __half g_wv2[512*1280];

__device__ __forceinline__ float silu_f(float v){ return v / (1.f + __expf(-v)); }
__device__ __forceinline__ uint32_t packh2(float a, float b){
    __half2 hh = __floats2half2_rn(a, b);
    return *(uint32_t*)&hh;
}

// ======================= conversion kernels =======================
__global__ void k_cvt_x(const float* __restrict__ x){
    __shared__ float t[32][33];
    int b = blockIdx.z, l0 = blockIdx.x<<5, c0 = blockIdx.y<<5;
    int tx = threadIdx.x, ty = threadIdx.y;
#pragma unroll
    for (int i=0;i<32;i+=8)
        t[ty+i][tx] = x[((size_t)((b<<9)+(c0+ty+i))<<12) + l0 + tx];
    __syncthreads();
#pragma unroll
    for (int i=0;i<32;i+=8){
        size_t o = ((size_t)((b<<12)+(l0+ty+i))<<9) + c0 + tx;
        g_xa[o] = __float2half(t[tx][ty+i]);
    }
}

__global__ void k_cvt_w(const float* __restrict__ cv1w, const float* __restrict__ cv2w,
                        const float* __restrict__ c0, const float* __restrict__ c1,
                        const float* __restrict__ c2, const float* __restrict__ c3,
                        const float* __restrict__ vw, const float* __restrict__ vb2,
                        const float* __restrict__ ow2, const float* __restrict__ ob2,
                        const float* __restrict__ aw2, const float* __restrict__ ab2,
                        const float* __restrict__ outw){
    int which = blockIdx.y;
    size_t i = (size_t)blockIdx.x*256 + threadIdx.x;
    if (which == 0){
        if (i >= (size_t)512*512) return;
        g_wcv1[i] = __float2half(cv1w[i]);
    } else if (which == 1){
        if (i >= (size_t)512*1280) return;
        g_wv2[i] = __float2half(cv2w[i]);
    } else if (which <= 5){
        if (i >= (size_t)256*2304) return;
        const float* src = (which==2)?c0:(which==3)?c1:(which==4)?c2:c3;
        __half *dh = (which==2)?g_wc0:(which==3)?g_wc1:(which==4)?g_wc2:g_wc3;
        int o = (int)(i / 2304);
        int k = (int)(i - (size_t)o*2304);
        int j = k >> 8, ic = k & 255;
        dh[i] = __float2half(src[((size_t)o*256 + ic)*9 + j]);
    } else if (which == 6){
        if (i >= (size_t)384*256) return;
        int n = (int)(i >> 8), c = (int)(i & 255);
        float v = 0.f;
        if (n < 256)       v = vw[(size_t)c*256 + n];
        else if (n < 320)  v = ow2[(size_t)c*64 + (n-256)];
        else if (n < 352)  v = aw2[(size_t)c*32 + (n-320)];
        g_wct[i] = __float2half(v);
        if (c == 0){
            float bv = 0.f;
            if (n < 256) bv = vb2[n];
            else if (n < 320) bv = ob2[n-256];
            else if (n < 352) bv = ab2[n-320];
            g_bct[n] = bv;
        }
    } else {
        if (i >= (size_t)256*256) return;
        int n = (int)(i >> 8), c = (int)(i & 255);
        g_wo[i] = __float2half(outw[(size_t)c*256 + n]);
    }
}

// ======================= main GEMM (pure fp16 mma.sync, fp32 accum) =======================
// CTA tile 128x128x64. 8 warps (2x4), warp tile 64x32.
// SMEM buffer (32KB): A 16KB (128 rows x 128B, SW128); B 16KB same. 3-deep ring, 2 CTAs/SM.
#define BUFB 32768
#define SMEM_BYTES (3*BUFB)

__global__ __launch_bounds__(256, 2) void k_gemm(int stage, const float* __restrict__ ebias,
                                                 float* __restrict__ dout)
{
    extern __shared__ char smc[];
    const uint32_t sb = smem_u32(smc);
    const int tid = threadIdx.x;
    const int wid = tid >> 5, lid = tid & 31;
    const int b  = blockIdx.z;
    const int l0 = blockIdx.y << 7;
    const int n0 = blockIdx.x << 7;

    int K;
    const __half* wgt;
    switch (stage){
        case 0: K = 512;  wgt = g_wcv1; break;
        case 1: K = 2304; wgt = g_wc0;  break;
        case 2: K = 2304; wgt = g_wc1;  break;
        case 3: K = 2304; wgt = g_wc2;  break;
        case 4: K = 2304; wgt = g_wc3;  break;
        case 5: K = 256;  wgt = g_wct;  break;
        case 6: K = 256;  wgt = g_wo;   break;
        default:K = 1280; wgt = g_wv2;  break;
    }
    const int NC = K >> 6;

    float acc[4][4][4];
#pragma unroll
    for (int i=0;i<4;i++)
#pragma unroll
    for (int j=0;j<4;j++)
#pragma unroll
    for (int e=0;e<4;e++) acc[i][j][e] = 0.f;

    const int wm = wid >> 2, wn = wid & 3;

    auto issue = [&](int cc){
        const __half *aa; int ach, acb, ady = 0, adx = 0; bool acv = false;
        const int k0c = cc << 6;
        if (stage == 0){ aa = g_xa; ach = 512; acb = k0c; }
        else if (stage <= 4){
            int j = cc >> 2; int jd = j / 3;
            ady = jd - 1; adx = j - jd*3 - 1; acv = true;
            int ic0 = (cc & 3) << 6;
            if (stage == 1){ aa = g_y0; ach = 512; acb = 256 + ic0; }
            else if (stage == 2){ aa = g_t0; ach = 256; acb = ic0; }
            else if (stage == 3){ aa = g_b1; ach = 256; acb = ic0; }
            else { aa = g_t1; ach = 256; acb = ic0; }
        }
        else if (stage == 5){ aa = g_b2; ach = 256; acb = k0c; }
        else if (stage == 6){ aa = g_sm; ach = 256; acb = k0c; }
        else {
            if (k0c < 512)      { aa = g_y0; ach = 512; acb = k0c; }
            else if (k0c < 768) { aa = g_b1; ach = 256; acb = k0c - 512; }
            else if (k0c < 1024){ aa = g_b2; ach = 256; acb = k0c - 768; }
            else                { aa = g_at; ach = 256; acb = k0c - 1024; }
        }
        uint32_t base = sb + (uint32_t)(cc % 3) * BUFB;
#pragma unroll
        for (int it2 = 0; it2 < 4; it2++){
            int it = tid + (it2 << 8);
            int m = it >> 3, u = it & 7;
            uint32_t o = ((uint32_t)m << 7) + ((uint32_t)u << 4);
            size_t off = 0; uint32_t nb = 16;
            if (acv){
                int p = l0 + m;
                int sy = (p >> 6) + ady, sx = (p & 63) + adx;
                if ((unsigned)sy < 64u && (unsigned)sx < 64u)
                    off = (size_t)((b<<12) + (sy<<6) + sx) * ach + acb + (u<<3);
                else nb = 0;
            } else {
                off = (size_t)((b<<12) + l0 + m) * ach + acb + (u<<3);
            }
            cpa16(base + SW128(o), aa + off, nb);
        }
#pragma unroll
        for (int it2 = 0; it2 < 4; it2++){
            int it = tid + (it2 << 8);
            int n = it >> 3, u = it & 7;
            uint32_t o = ((uint32_t)n << 7) + ((uint32_t)u << 4);
            size_t woff = (size_t)(n0 + n) * K + k0c + (u << 3);
            cpa16(base + 16384 + SW128(o), wgt + woff, 16);
        }
        CP_COMMIT();
    };

    issue(0);
    issue(1);
    for (int cc = 0; cc < NC; cc++){
        CP_WAIT1();
        __syncthreads();
        if (cc + 2 < NC) issue(cc + 2);
        uint32_t ua = sb + (uint32_t)(cc % 3) * BUFB;
        uint32_t ub = ua + 16384u;
        const int mat = lid >> 3, r8 = lid & 7;
#pragma unroll
        for (int ks = 0; ks < 4; ks++){
            uint32_t af[4][4], bf[2][4];
#pragma unroll
            for (int mi = 0; mi < 4; mi++){
                int row = (wm << 6) + (mi << 4) + ((mat & 1) << 3) + r8;
                uint32_t o = ((uint32_t)row << 7) + (ks << 5) + ((mat >> 1) << 4);
                ldsm4(af[mi], ua + SW128(o));
            }
#pragma unroll
            for (int bi = 0; bi < 2; bi++){
                int row = (wn << 5) + (bi << 4) + ((mat >> 1) << 3) + r8;
                uint32_t o = ((uint32_t)row << 7) + (ks << 5) + ((mat & 1) << 4);
                ldsm4(bf[bi], ub + SW128(o));
            }
#pragma unroll
            for (int mi = 0; mi < 4; mi++)
#pragma unroll
            for (int ni = 0; ni < 4; ni++)
                mma16816(acc[mi][ni], af[mi],
                         bf[ni >> 1][(ni & 1) << 1], bf[ni >> 1][((ni & 1) << 1) + 1]);
        }
    }

    // ---------------- epilogue ----------------
    const int qr = lid >> 2;
    const int qc = (lid & 3) << 1;
#pragma unroll
    for (int mi = 0; mi < 4; mi++){
#pragma unroll
        for (int ni = 0; ni < 4; ni++){
            float* c = acc[mi][ni];
            int ch = (wn << 5) + (ni << 3) + qc;
            int r0 = (wm << 6) + (mi << 4) + qr;
            int r1 = r0 + 8;

            if (stage <= 4){
                __half* dd; int OC;
                if (stage == 0){ dd = g_y0; OC = 512; }
                else if (stage == 1){ dd = g_t0; OC = 256; }
                else if (stage == 2){ dd = g_b1; OC = 256; }
                else if (stage == 3){ dd = g_t1; OC = 256; }
                else { dd = g_b2; OC = 256; }
#pragma unroll
                for (int h2 = 0; h2 < 2; h2++){
                    int r = h2 ? r1 : r0;
                    size_t o = ((size_t)((b<<12) + l0 + r)) * OC + n0 + ch;
                    *(uint32_t*)&dd[o] = packh2(silu_f(c[2*h2]), silu_f(c[2*h2+1]));
                }
            } else if (stage == 5){
#pragma unroll
                for (int h2 = 0; h2 < 2; h2++){
                    int r = h2 ? r1 : r0;
                    size_t bl2 = (size_t)(b<<12) + l0 + r;
                    int ng = n0 + ch;
                    float v0 = c[2*h2]     + g_bct[ng];
                    float v1 = c[2*h2 + 1] + g_bct[ng + 1];
                    if (ng < 256){
                        *(uint32_t*)&g_value[bl2*256 + ng] = packh2(v0, v1);
                    } else if (ng < 320){
                        g_off[bl2*64 + (ng - 256)] = v0;
                        g_off[bl2*64 + (ng - 255)] = v1;
                    } else if (ng < 352){
                        g_awL[bl2*32 + (ng - 320)] = v0;
                        g_awL[bl2*32 + (ng - 319)] = v1;
                    }
                }
            } else if (stage == 6){
#pragma unroll
                for (int h2 = 0; h2 < 2; h2++){
                    int r = h2 ? r1 : r0;
                    float v0 = c[2*h2]     + ebias[n0 + ch];
                    float v1 = c[2*h2 + 1] + ebias[n0 + ch + 1];
                    size_t o = ((size_t)((b<<12) + l0 + r)) * 256 + n0 + ch;
                    *(uint32_t*)&g_at[o] = packh2(v0, v1);
                }
            } else {
#pragma unroll
                for (int h2 = 0; h2 < 2; h2++){
                    int r = h2 ? r1 : r0;
#pragma unroll
                    for (int e = 0; e < 2; e++){
                        float v = silu_f(c[2*h2 + e]);
                        dout[((size_t)((b << 9) + n0 + ch + e) << 12) + l0 + r] = v;
                    }
                }
            }
        }
    }
}

// ======================= deformable sampling (fp16 value gathers) =======================
__global__ void k_sample(const float* __restrict__ bbox){
    int g = blockIdx.x * blockDim.x + threadIdx.x;
    if (g >= NB * LP * 64) return;
    int d4 = g & 7;
    int hd = (g >> 3) & 7;
    int l  = (g >> 6) & 4095;
    int b  = g >> 18;
    size_t bl = (size_t)b * LP + l;
    float bx = bbox[bl*2 + 0];
    float by = bbox[bl*2 + 1];
    const float* op = g_off + bl*64 + hd*8;
    const float* ap = g_awL + bl*32 + hd*4;

    float a0 = ap[0], a1 = ap[1], a2 = ap[2], a3 = ap[3];
    float mx = fmaxf(fmaxf(a0, a1), fmaxf(a2, a3));
    float e0 = __expf(a0 - mx), e1 = __expf(a1 - mx), e2 = __expf(a2 - mx), e3 = __expf(a3 - mx);
    float inv = 1.f / (e0 + e1 + e2 + e3);
    float wp[4] = {e0*inv, e1*inv, e2*inv, e3*inv};

    const __half* vb = g_value + ((size_t)b * LP) * 256 + hd*32 + (d4 << 2);
    float4 acc = make_float4(0.f, 0.f, 0.f, 0.f);
#pragma unroll
    for (int p = 0; p < 4; p++){
        float lx = bx + op[p*2 + 0] * 0.015625f;
        float ly = by + op[p*2 + 1] * 0.015625f;
        float gx = lx * 64.f - 0.5f;
        float gy = ly * 64.f - 0.5f;
        float fx = floorf(gx), fy = floorf(gy);
        float wx1 = gx - fx, wy1 = gy - fy;
        float wx0 = 1.f - wx1, wy0 = 1.f - wy1;
        int ix = (int)fx, iy = (int)fy;
        float awp = wp[p];
#pragma unroll
        for (int c2 = 0; c2 < 4; c2++){
            int cx = ix + (c2 & 1);
            int cy = iy + (c2 >> 1);
            if ((unsigned)cx < 64u && (unsigned)cy < 64u){
                float wgt = awp * ((c2 & 1) ? wx1 : wx0) * ((c2 >> 1) ? wy1 : wy0);
                // 8-byte gather: 4 halves
                uint2 raw = *(const uint2*)&vb[(size_t)((cy << 6) + cx) * 256];
                __half2 v01 = *(__half2*)&raw.x;
                __half2 v23 = *(__half2*)&raw.y;
                float2 f01 = __half22float2(v01);
                float2 f23 = __half22float2(v23);
                acc.x += wgt * f01.x; acc.y += wgt * f01.y;
                acc.z += wgt * f23.x; acc.w += wgt * f23.y;
            }
        }
    }
    size_t o = bl*256 + hd*32 + (d4 << 2);
    *(uint32_t*)&g_sm[o]     = packh2(acc.x, acc.y);
    *(uint32_t*)&g_sm[o + 2] = packh2(acc.z, acc.w);
}

// ======================= launch =======================
extern "C" void kernel_launch(void* const* d_in, const int* in_sizes, int n_in,
                              void* d_out, int out_size) {
    const float* x    = (const float*)d_in[0];
    const float* bbox = (const float*)d_in[1];
    const float* cv1w = (const float*)d_in[3];
    const float* m0c1 = (const float*)d_in[4];
    const float* m0c2 = (const float*)d_in[5];
    const float* m1c1 = (const float*)d_in[6];
    const float* m1c2 = (const float*)d_in[7];
    const float* vw   = (const float*)d_in[8];
    const float* vb   = (const float*)d_in[9];
    const float* ow   = (const float*)d_in[10];
    const float* ob   = (const float*)d_in[11];
    const float* aww  = (const float*)d_in[12];
    const float* awb  = (const float*)d_in[13];
    const float* outw = (const float*)d_in[14];
    const float* outb = (const float*)d_in[15];
    const float* cv2w = (const float*)d_in[16];

    cudaFuncSetAttribute(k_gemm, cudaFuncAttributeMaxDynamicSharedMemorySize, SMEM_BYTES);

    k_cvt_x<<<dim3(128, 16, NB), dim3(32, 8)>>>(x);
    k_cvt_w<<<dim3(2560, 8), 256>>>(cv1w, cv2w, m0c1, m0c2, m1c1, m1c2,
                                    vw, vb, ow, ob, aww, awb, outw);

    k_gemm<<<dim3(4, 32, NB), 256, SMEM_BYTES>>>(0, nullptr, nullptr);   // cv1
    k_gemm<<<dim3(2, 32, NB), 256, SMEM_BYTES>>>(1, nullptr, nullptr);   // m0_cv1
    k_gemm<<<dim3(2, 32, NB), 256, SMEM_BYTES>>>(2, nullptr, nullptr);   // m0_cv2
    k_gemm<<<dim3(2, 32, NB), 256, SMEM_BYTES>>>(3, nullptr, nullptr);   // m1_cv1
    k_gemm<<<dim3(2, 32, NB), 256, SMEM_BYTES>>>(4, nullptr, nullptr);   // m1_cv2
    k_gemm<<<dim3(3, 32, NB), 256, SMEM_BYTES>>>(5, nullptr, nullptr);   // fused projections
    k_sample<<<(NB * LP * 64 + 255) / 256, 256>>>(bbox);
    k_gemm<<<dim3(2, 32, NB), 256, SMEM_BYTES>>>(6, outb, nullptr);      // out projection
    k_gemm<<<dim3(4, 32, NB), 256, SMEM_BYTES>>>(7, nullptr, (float*)d_out); // cv2
}